// round 1
// baseline (speedup 1.0000x reference)
#include <cuda_runtime.h>
#include <cuda_bf16.h>
#include <math.h>

#define NN 50000
#define EE 1600000
#define H  64
#define CC 16

// ---- device scratch (allocation-free rule: static globals) ----
__device__ float g_h[NN * H];        // linear output of current layer
__device__ float g_agg[NN * H];      // scatter accumulator (must be zero at entry; re-zeroed by epilogue)
__device__ float g_emb[NN * 3 * H];  // concat of the 3 normalized layer outputs
__device__ int   g_deg[NN];          // in-degree counter (re-zeroed by dis kernel)
__device__ float g_dis[NN];          // rsqrt(deg + 1)

// ---------------------------------------------------------------
// 1) in-degree histogram over target nodes
__global__ void k_hist(const int* __restrict__ rows) {
    int e = blockIdx.x * blockDim.x + threadIdx.x;
    if (e < EE) atomicAdd(&g_deg[rows[e]], 1);
}

// 2) dis = rsqrt(deg + 1)  (self-loop included -> deg >= 1 always); reset deg for next replay
__global__ void k_dis() {
    int i = blockIdx.x * blockDim.x + threadIdx.x;
    if (i < NN) {
        g_dis[i] = rsqrtf((float)(g_deg[i] + 1));
        g_deg[i] = 0;
    }
}

// ---------------------------------------------------------------
// 3) h = in @ W   (in: [N, stride] fp32, W: [64,64] row-major fan_in x fan_out)
//    src: 0 -> external x (stride 64), 1 -> g_emb+0 (stride 192), 2 -> g_emb+64 (stride 192)
__global__ void k_matmul(const float* __restrict__ x, int src, const float* __restrict__ W) {
    __shared__ float Ws[64][64];
    __shared__ float xs[4][64];
    int j  = threadIdx.x & 63;   // output col
    int nl = threadIdx.x >> 6;   // local row 0..3
    for (int i = threadIdx.x; i < 64 * 64; i += 256)
        Ws[i >> 6][i & 63] = W[i];

    const float* in; int stride;
    if (src == 0)      { in = x;            stride = 64;  }
    else if (src == 1) { in = g_emb;        stride = 192; }
    else               { in = g_emb + 64;   stride = 192; }

    int n = blockIdx.x * 4 + nl;                 // N divisible by 4
    xs[nl][j] = in[(size_t)n * stride + j];
    __syncthreads();

    float acc = 0.f;
#pragma unroll
    for (int k = 0; k < 64; k++)
        acc = fmaf(xs[nl][k], Ws[k][j], acc);
    g_h[n * 64 + j] = acc;
}

// ---------------------------------------------------------------
// 4) edge scatter: agg[row] += dis[row]*dis[col] * h[col]
//    16 threads per edge, float4 per thread, vector red.global.add.v4.f32
__global__ void k_scatter(const int* __restrict__ rows, const int* __restrict__ cols) {
    int tid = blockIdx.x * blockDim.x + threadIdx.x;
    int e = tid >> 4;
    int t = tid & 15;
    if (e >= EE) return;
    int r = rows[e];
    int c = cols[e];
    float nm = g_dis[r] * g_dis[c];
    float4 v = *(const float4*)(g_h + c * 64 + t * 4);
    v.x *= nm; v.y *= nm; v.z *= nm; v.w *= nm;
    float* dst = g_agg + r * 64 + t * 4;
    asm volatile("red.global.add.v4.f32 [%0], {%1,%2,%3,%4};"
                 :: "l"(dst), "f"(v.x), "f"(v.y), "f"(v.z), "f"(v.w)
                 : "memory");
}

// ---------------------------------------------------------------
// 5) epilogue: v = agg + dis^2 * h (self loop) + b ; relu ; L2-normalize ;
//    write into emb[:, off:off+64] ; zero agg for next layer / next replay.
//    one warp per node, 2 floats per lane.
__global__ void k_epilogue(const float* __restrict__ b, int off) {
    int warp = (blockIdx.x * blockDim.x + threadIdx.x) >> 5;
    int lane = threadIdx.x & 31;
    if (warp >= NN) return;
    float d  = g_dis[warp];
    float d2 = d * d;
    float2 a  = *(const float2*)(g_agg + warp * 64 + lane * 2);
    float2 h  = *(const float2*)(g_h   + warp * 64 + lane * 2);
    float2 bb = *(const float2*)(b + lane * 2);
    float vx = fmaxf(fmaf(d2, h.x, a.x) + bb.x, 0.f);
    float vy = fmaxf(fmaf(d2, h.y, a.y) + bb.y, 0.f);
    float s = vx * vx + vy * vy;
#pragma unroll
    for (int m = 16; m >= 1; m >>= 1)
        s += __shfl_xor_sync(0xFFFFFFFFu, s, m);
    float n   = sqrtf(s);
    float inv = 1.f / fmaxf(n, 1e-12f);
    float2 o; o.x = vx * inv; o.y = vy * inv;
    *(float2*)(g_emb + (size_t)warp * 192 + off + lane * 2) = o;
    float2 z; z.x = 0.f; z.y = 0.f;
    *(float2*)(g_agg + warp * 64 + lane * 2) = z;
}

// ---------------------------------------------------------------
// 6) out = log_softmax(emb @ Wlin + blin). 16 lanes per node (2 nodes/warp).
__global__ void k_final(const float* __restrict__ Wlin, const float* __restrict__ blin,
                        float* __restrict__ out) {
    __shared__ float Ws[192 * 16];
    for (int i = threadIdx.x; i < 192 * 16; i += 256) Ws[i] = Wlin[i];
    __syncthreads();
    int n = blockIdx.x * 16 + (threadIdx.x >> 4);   // N divisible by 16
    int c = threadIdx.x & 15;
    const float* e = g_emb + (size_t)n * 192;
    float acc = blin[c];
#pragma unroll 8
    for (int k = 0; k < 192; k++)
        acc = fmaf(e[k], Ws[k * 16 + c], acc);
    // log_softmax across the 16-lane group (xor widths < 16 stay in-group)
    float m = acc;
#pragma unroll
    for (int s = 8; s >= 1; s >>= 1)
        m = fmaxf(m, __shfl_xor_sync(0xFFFFFFFFu, m, s));
    float ex = __expf(acc - m);
    float sum = ex;
#pragma unroll
    for (int s = 8; s >= 1; s >>= 1)
        sum += __shfl_xor_sync(0xFFFFFFFFu, sum, s);
    out[n * 16 + c] = acc - m - logf(sum);
}

// ---------------------------------------------------------------
extern "C" void kernel_launch(void* const* d_in, const int* in_sizes, int n_in,
                              void* d_out, int out_size) {
    const float* x    = (const float*)d_in[0];
    const int*   ei   = (const int*)  d_in[1];   // [2, E] row-major
    const float* W1   = (const float*)d_in[2];
    const float* b1   = (const float*)d_in[3];
    const float* W2   = (const float*)d_in[4];
    const float* b2   = (const float*)d_in[5];
    const float* W3   = (const float*)d_in[6];
    const float* b3   = (const float*)d_in[7];
    const float* Wlin = (const float*)d_in[8];
    const float* blin = (const float*)d_in[9];
    float* out = (float*)d_out;

    const int* rows = ei;        // targets
    const int* cols = ei + EE;   // sources

    k_hist<<<(EE + 255) / 256, 256>>>(rows);
    k_dis <<<(NN + 255) / 256, 256>>>();

    const float* Wb[3][2] = { {W1, b1}, {W2, b2}, {W3, b3} };
    for (int L = 0; L < 3; L++) {
        k_matmul  <<<NN / 4, 256>>>(x, L, Wb[L][0]);
        k_scatter <<<(EE * 16) / 256, 256>>>(rows, cols);
        k_epilogue<<<(NN * 32) / 256, 256>>>(Wb[L][1], L * 64);
    }
    k_final<<<NN / 16, 256>>>(Wlin, blin, out);
}

// round 2
// speedup vs baseline: 1.3315x; 1.3315x over previous
#include <cuda_runtime.h>
#include <cuda_bf16.h>
#include <math.h>

#define NN 50000
#define EE 1600000
#define H  64
#define CC 16
#define NBLK 196            // ceil(NN/256)

// ---- device scratch (allocation-free rule: static globals) ----
__device__ float g_h[NN * H];          // linear output of current layer
__device__ float g_emb[NN * 3 * H];    // concat of the 3 normalized layer outputs
__device__ int   g_deg[NN];            // in-degree counter (re-zeroed by finalize)
__device__ float g_dis[NN];            // rsqrt(deg + 1)
__device__ int   g_off[NN + 1];        // CSR row offsets
__device__ int   g_cur[NN];            // placement cursors
__device__ int   g_bsum[NBLK];         // per-block degree sums
__device__ int   g_bpre[NBLK];         // exclusive prefix of block sums
__device__ int   g_ecol[EE];           // CSR: source node per edge
__device__ float g_enorm[EE];          // CSR: dis[r]*dis[c] per edge

// ---------------------------------------------------------------
// 1) in-degree histogram over target nodes
__global__ void k_hist(const int* __restrict__ rows) {
    int e = blockIdx.x * blockDim.x + threadIdx.x;
    if (e < EE) atomicAdd(&g_deg[rows[e]], 1);
}

// 2a) per-block sums of deg
__global__ void k_blocksum() {
    __shared__ int s[256];
    int i = blockIdx.x * 256 + threadIdx.x;
    int v = (i < NN) ? g_deg[i] : 0;
    s[threadIdx.x] = v;
    __syncthreads();
    for (int m = 128; m >= 1; m >>= 1) {
        if (threadIdx.x < m) s[threadIdx.x] += s[threadIdx.x + m];
        __syncthreads();
    }
    if (threadIdx.x == 0) g_bsum[blockIdx.x] = s[0];
}

// 2b) serial exclusive scan of 196 block sums (tiny)
__global__ void k_scanbsum() {
    if (threadIdx.x == 0) {
        int acc = 0;
        for (int i = 0; i < NBLK; i++) { g_bpre[i] = acc; acc += g_bsum[i]; }
    }
}

// 2c) finalize: in-block exclusive scan -> g_off, g_cur; dis; zero deg for replay
__global__ void k_finalize() {
    __shared__ int s[256];
    int i = blockIdx.x * 256 + threadIdx.x;
    int d = (i < NN) ? g_deg[i] : 0;
    s[threadIdx.x] = d;
    __syncthreads();
    // Hillis-Steele inclusive scan
    for (int m = 1; m < 256; m <<= 1) {
        int t = (threadIdx.x >= m) ? s[threadIdx.x - m] : 0;
        __syncthreads();
        s[threadIdx.x] += t;
        __syncthreads();
    }
    if (i < NN) {
        int excl = g_bpre[blockIdx.x] + s[threadIdx.x] - d;
        g_off[i] = excl;
        g_cur[i] = excl;
        g_dis[i] = rsqrtf((float)(d + 1));
        g_deg[i] = 0;
    }
    if (i == 0) g_off[NN] = EE;
}

// 3) place edges into CSR slots; precompute per-edge norm
__global__ void k_place(const int* __restrict__ rows, const int* __restrict__ cols) {
    int e = blockIdx.x * blockDim.x + threadIdx.x;
    if (e >= EE) return;
    int r = rows[e];
    int c = cols[e];
    int pos = atomicAdd(&g_cur[r], 1);
    g_ecol[pos]  = c;
    g_enorm[pos] = g_dis[r] * g_dis[c];
}

// ---------------------------------------------------------------
// 4) h = in @ W   (in: [N, stride] fp32, W: [64,64] row-major fan_in x fan_out)
__global__ void k_matmul(const float* __restrict__ x, int src, const float* __restrict__ W) {
    __shared__ float Ws[64][64];
    __shared__ float xs[4][64];
    int j  = threadIdx.x & 63;
    int nl = threadIdx.x >> 6;
    for (int i = threadIdx.x; i < 64 * 64; i += 256)
        Ws[i >> 6][i & 63] = W[i];

    const float* in; int stride;
    if (src == 0)      { in = x;          stride = 64;  }
    else if (src == 1) { in = g_emb;      stride = 192; }
    else               { in = g_emb + 64; stride = 192; }

    int n = blockIdx.x * 4 + nl;
    xs[nl][j] = in[(size_t)n * stride + j];
    __syncthreads();

    float acc = 0.f;
#pragma unroll
    for (int k = 0; k < 64; k++)
        acc = fmaf(xs[nl][k], Ws[k][j], acc);
    g_h[n * 64 + j] = acc;
}

// ---------------------------------------------------------------
// 5) fused CSR aggregate + self-loop + bias + relu + L2norm + emb write.
//    one warp per node, float2 per lane.
__global__ void k_agg(const float* __restrict__ b, int off) {
    int node = (blockIdx.x * blockDim.x + threadIdx.x) >> 5;
    int lane = threadIdx.x & 31;
    if (node >= NN) return;

    int s = g_off[node];
    int e = g_off[node + 1];
    float accx = 0.f, accy = 0.f;

    int i = s;
    for (; i + 4 <= e; i += 4) {
        int   c0 = g_ecol[i+0], c1 = g_ecol[i+1], c2 = g_ecol[i+2], c3 = g_ecol[i+3];
        float n0 = g_enorm[i+0], n1 = g_enorm[i+1], n2 = g_enorm[i+2], n3 = g_enorm[i+3];
        float2 v0 = *(const float2*)(g_h + c0 * 64 + lane * 2);
        float2 v1 = *(const float2*)(g_h + c1 * 64 + lane * 2);
        float2 v2 = *(const float2*)(g_h + c2 * 64 + lane * 2);
        float2 v3 = *(const float2*)(g_h + c3 * 64 + lane * 2);
        accx = fmaf(n0, v0.x, accx); accy = fmaf(n0, v0.y, accy);
        accx = fmaf(n1, v1.x, accx); accy = fmaf(n1, v1.y, accy);
        accx = fmaf(n2, v2.x, accx); accy = fmaf(n2, v2.y, accy);
        accx = fmaf(n3, v3.x, accx); accy = fmaf(n3, v3.y, accy);
    }
    for (; i < e; i++) {
        int   c = g_ecol[i];
        float n = g_enorm[i];
        float2 v = *(const float2*)(g_h + c * 64 + lane * 2);
        accx = fmaf(n, v.x, accx); accy = fmaf(n, v.y, accy);
    }

    // self loop + bias + relu
    float d  = g_dis[node];
    float d2 = d * d;
    float2 hh = *(const float2*)(g_h + node * 64 + lane * 2);
    float bx = b[lane * 2], by = b[lane * 2 + 1];
    float vx = fmaxf(fmaf(d2, hh.x, accx) + bx, 0.f);
    float vy = fmaxf(fmaf(d2, hh.y, accy) + by, 0.f);

    // L2 normalize across warp
    float ss = vx * vx + vy * vy;
#pragma unroll
    for (int m = 16; m >= 1; m >>= 1)
        ss += __shfl_xor_sync(0xFFFFFFFFu, ss, m);
    float inv = 1.f / fmaxf(sqrtf(ss), 1e-12f);
    float2 o; o.x = vx * inv; o.y = vy * inv;
    *(float2*)(g_emb + (size_t)node * 192 + off + lane * 2) = o;
}

// ---------------------------------------------------------------
// 6) out = log_softmax(emb @ Wlin + blin). 16 lanes per node.
__global__ void k_final(const float* __restrict__ Wlin, const float* __restrict__ blin,
                        float* __restrict__ out) {
    __shared__ float Ws[192 * 16];
    for (int i = threadIdx.x; i < 192 * 16; i += 256) Ws[i] = Wlin[i];
    __syncthreads();
    int n = blockIdx.x * 16 + (threadIdx.x >> 4);
    int c = threadIdx.x & 15;
    const float* e = g_emb + (size_t)n * 192;
    float acc = blin[c];
#pragma unroll 8
    for (int k = 0; k < 192; k++)
        acc = fmaf(e[k], Ws[k * 16 + c], acc);
    float m = acc;
#pragma unroll
    for (int s = 8; s >= 1; s >>= 1)
        m = fmaxf(m, __shfl_xor_sync(0xFFFFFFFFu, m, s));
    float ex = __expf(acc - m);
    float sum = ex;
#pragma unroll
    for (int s = 8; s >= 1; s >>= 1)
        sum += __shfl_xor_sync(0xFFFFFFFFu, sum, s);
    out[n * 16 + c] = acc - m - logf(sum);
}

// ---------------------------------------------------------------
extern "C" void kernel_launch(void* const* d_in, const int* in_sizes, int n_in,
                              void* d_out, int out_size) {
    const float* x    = (const float*)d_in[0];
    const int*   ei   = (const int*)  d_in[1];
    const float* W1   = (const float*)d_in[2];
    const float* b1   = (const float*)d_in[3];
    const float* W2   = (const float*)d_in[4];
    const float* b2   = (const float*)d_in[5];
    const float* W3   = (const float*)d_in[6];
    const float* b3   = (const float*)d_in[7];
    const float* Wlin = (const float*)d_in[8];
    const float* blin = (const float*)d_in[9];
    float* out = (float*)d_out;

    const int* rows = ei;        // targets
    const int* cols = ei + EE;   // sources

    // ---- CSR build ----
    k_hist     <<<(EE + 255) / 256, 256>>>(rows);
    k_blocksum <<<NBLK, 256>>>();
    k_scanbsum <<<1, 32>>>();
    k_finalize <<<NBLK, 256>>>();
    k_place    <<<(EE + 255) / 256, 256>>>(rows, cols);

    // ---- 3 GCN layers ----
    const float* Wb[3][2] = { {W1, b1}, {W2, b2}, {W3, b3} };
    for (int L = 0; L < 3; L++) {
        k_matmul<<<NN / 4, 256>>>(x, L, Wb[L][0]);
        k_agg   <<<(NN * 32 + 255) / 256, 256>>>(Wb[L][1], L * 64);
    }
    k_final<<<NN / 16, 256>>>(Wlin, blin, out);
}

// round 3
// speedup vs baseline: 2.1163x; 1.5894x over previous
#include <cuda_runtime.h>
#include <cuda_bf16.h>
#include <math.h>

#define NN 50000
#define EE 1600000
#define H  64
#define CC 16
#define NBLK 196            // ceil(NN/256)

// ---- device scratch (allocation-free rule: static globals) ----
__device__ float g_h[NN * H];          // linear output of current layer
__device__ float g_emb[NN * 3 * H];    // concat of the 3 normalized layer outputs
__device__ int   g_deg[NN];            // in-degree counter (re-zeroed by finalize)
__device__ float g_dis[NN];            // rsqrt(deg + 1)
__device__ int   g_off[NN + 1];        // CSR row offsets
__device__ int   g_cur[NN];            // placement cursors
__device__ int   g_bsum[NBLK];         // per-block degree sums
__device__ int   g_bpre[NBLK];         // exclusive prefix of block sums
__device__ int2  g_edge[EE];           // CSR: {source node, norm bits} per edge

// ---------------------------------------------------------------
// 1) in-degree histogram over target nodes
__global__ void k_hist(const int* __restrict__ rows) {
    int e = blockIdx.x * blockDim.x + threadIdx.x;
    if (e < EE) atomicAdd(&g_deg[rows[e]], 1);
}

// 2a) per-block sums of deg
__global__ void k_blocksum() {
    __shared__ int s[256];
    int i = blockIdx.x * 256 + threadIdx.x;
    int v = (i < NN) ? g_deg[i] : 0;
    s[threadIdx.x] = v;
    __syncthreads();
    for (int m = 128; m >= 1; m >>= 1) {
        if (threadIdx.x < m) s[threadIdx.x] += s[threadIdx.x + m];
        __syncthreads();
    }
    if (threadIdx.x == 0) g_bsum[blockIdx.x] = s[0];
}

// 2b) parallel exclusive scan of NBLK block sums (single block)
__global__ void k_scanbsum() {
    __shared__ int s[256];
    int t = threadIdx.x;
    int v = (t < NBLK) ? g_bsum[t] : 0;
    s[t] = v;
    __syncthreads();
    for (int m = 1; m < 256; m <<= 1) {
        int u = (t >= m) ? s[t - m] : 0;
        __syncthreads();
        s[t] += u;
        __syncthreads();
    }
    if (t < NBLK) g_bpre[t] = s[t] - v;
}

// 2c) finalize: in-block exclusive scan -> g_off, g_cur; dis; zero deg for replay
__global__ void k_finalize() {
    __shared__ int s[256];
    int i = blockIdx.x * 256 + threadIdx.x;
    int d = (i < NN) ? g_deg[i] : 0;
    s[threadIdx.x] = d;
    __syncthreads();
    for (int m = 1; m < 256; m <<= 1) {
        int t = (threadIdx.x >= m) ? s[threadIdx.x - m] : 0;
        __syncthreads();
        s[threadIdx.x] += t;
        __syncthreads();
    }
    if (i < NN) {
        int excl = g_bpre[blockIdx.x] + s[threadIdx.x] - d;
        g_off[i] = excl;
        g_cur[i] = excl;
        g_dis[i] = rsqrtf((float)(d + 1));
        g_deg[i] = 0;
    }
    if (i == 0) g_off[NN] = EE;
}

// 3) place edges into CSR slots; precompute per-edge norm; pack 8B
__global__ void k_place(const int* __restrict__ rows, const int* __restrict__ cols) {
    int e = blockIdx.x * blockDim.x + threadIdx.x;
    if (e >= EE) return;
    int r = rows[e];
    int c = cols[e];
    int pos = atomicAdd(&g_cur[r], 1);
    int2 rec;
    rec.x = c;
    rec.y = __float_as_int(g_dis[r] * g_dis[c]);
    g_edge[pos] = rec;
}

// ---------------------------------------------------------------
// 4) h = in @ W, register-tiled: 64 nodes x 64 cols per block, 4x4 per thread.
__global__ void k_matmul(const float* __restrict__ x, int src, const float* __restrict__ W) {
    __shared__ float Ws[64 * 64];
    __shared__ float xs[64][65];
    int tid = threadIdx.x;

    const float* in; int stride;
    if (src == 0)      { in = x;          stride = 64;  }
    else if (src == 1) { in = g_emb;      stride = 192; }
    else               { in = g_emb + 64; stride = 192; }

    int n0 = blockIdx.x * 64;
    for (int i = tid; i < 64 * 64; i += 256) Ws[i] = W[i];
    {
        int col = tid & 63;
        int rbase = (tid >> 6) * 16;
#pragma unroll
        for (int r = 0; r < 16; r++) {
            int row = rbase + r;
            int n = n0 + row;
            xs[row][col] = (n < NN) ? in[(size_t)n * stride + col] : 0.f;
        }
    }
    __syncthreads();

    int tj = (tid & 15) * 4;   // output col base
    int tn = (tid >> 4) * 4;   // node base (local)
    float acc[4][4];
#pragma unroll
    for (int i = 0; i < 4; i++)
#pragma unroll
        for (int j = 0; j < 4; j++) acc[i][j] = 0.f;

#pragma unroll 8
    for (int k = 0; k < 64; k++) {
        float4 w = *(const float4*)&Ws[k * 64 + tj];
        float x0 = xs[tn + 0][k];
        float x1 = xs[tn + 1][k];
        float x2 = xs[tn + 2][k];
        float x3 = xs[tn + 3][k];
        acc[0][0] = fmaf(x0, w.x, acc[0][0]); acc[0][1] = fmaf(x0, w.y, acc[0][1]);
        acc[0][2] = fmaf(x0, w.z, acc[0][2]); acc[0][3] = fmaf(x0, w.w, acc[0][3]);
        acc[1][0] = fmaf(x1, w.x, acc[1][0]); acc[1][1] = fmaf(x1, w.y, acc[1][1]);
        acc[1][2] = fmaf(x1, w.z, acc[1][2]); acc[1][3] = fmaf(x1, w.w, acc[1][3]);
        acc[2][0] = fmaf(x2, w.x, acc[2][0]); acc[2][1] = fmaf(x2, w.y, acc[2][1]);
        acc[2][2] = fmaf(x2, w.z, acc[2][2]); acc[2][3] = fmaf(x2, w.w, acc[2][3]);
        acc[3][0] = fmaf(x3, w.x, acc[3][0]); acc[3][1] = fmaf(x3, w.y, acc[3][1]);
        acc[3][2] = fmaf(x3, w.z, acc[3][2]); acc[3][3] = fmaf(x3, w.w, acc[3][3]);
    }

#pragma unroll
    for (int i = 0; i < 4; i++) {
        int n = n0 + tn + i;
        if (n < NN) {
            float4 o; o.x = acc[i][0]; o.y = acc[i][1]; o.z = acc[i][2]; o.w = acc[i][3];
            *(float4*)&g_h[n * 64 + tj] = o;
        }
    }
}

// ---------------------------------------------------------------
// 5) fused CSR aggregate + self-loop + bias + relu + L2norm + emb write.
//    one warp per node, float2 per lane.
__global__ void k_agg(const float* __restrict__ b, int off) {
    int node = (blockIdx.x * blockDim.x + threadIdx.x) >> 5;
    int lane = threadIdx.x & 31;
    if (node >= NN) return;

    int s = g_off[node];
    int e = g_off[node + 1];
    float accx = 0.f, accy = 0.f;

    int i = s;
    for (; i + 4 <= e; i += 4) {
        int2 e0 = g_edge[i + 0];
        int2 e1 = g_edge[i + 1];
        int2 e2 = g_edge[i + 2];
        int2 e3 = g_edge[i + 3];
        float2 v0 = *(const float2*)(g_h + e0.x * 64 + lane * 2);
        float2 v1 = *(const float2*)(g_h + e1.x * 64 + lane * 2);
        float2 v2 = *(const float2*)(g_h + e2.x * 64 + lane * 2);
        float2 v3 = *(const float2*)(g_h + e3.x * 64 + lane * 2);
        float n0 = __int_as_float(e0.y), n1 = __int_as_float(e1.y);
        float n2 = __int_as_float(e2.y), n3 = __int_as_float(e3.y);
        accx = fmaf(n0, v0.x, accx); accy = fmaf(n0, v0.y, accy);
        accx = fmaf(n1, v1.x, accx); accy = fmaf(n1, v1.y, accy);
        accx = fmaf(n2, v2.x, accx); accy = fmaf(n2, v2.y, accy);
        accx = fmaf(n3, v3.x, accx); accy = fmaf(n3, v3.y, accy);
    }
    for (; i < e; i++) {
        int2 ed = g_edge[i];
        float2 v = *(const float2*)(g_h + ed.x * 64 + lane * 2);
        float n = __int_as_float(ed.y);
        accx = fmaf(n, v.x, accx); accy = fmaf(n, v.y, accy);
    }

    float d  = g_dis[node];
    float d2 = d * d;
    float2 hh = *(const float2*)(g_h + node * 64 + lane * 2);
    float bx = b[lane * 2], by = b[lane * 2 + 1];
    float vx = fmaxf(fmaf(d2, hh.x, accx) + bx, 0.f);
    float vy = fmaxf(fmaf(d2, hh.y, accy) + by, 0.f);

    float ss = vx * vx + vy * vy;
#pragma unroll
    for (int m = 16; m >= 1; m >>= 1)
        ss += __shfl_xor_sync(0xFFFFFFFFu, ss, m);
    float inv = 1.f / fmaxf(sqrtf(ss), 1e-12f);
    float2 o; o.x = vx * inv; o.y = vy * inv;
    *(float2*)(g_emb + (size_t)node * 192 + off + lane * 2) = o;
}

// ---------------------------------------------------------------
// 6) out = log_softmax(emb @ Wlin + blin).
//    Register-tiled: 64 nodes per block; thread = 1 class x 4 nodes.
__global__ void k_final(const float* __restrict__ Wlin, const float* __restrict__ blin,
                        float* __restrict__ out) {
    __shared__ float Ws[192 * 16];
    __shared__ float es[64][193];
    int tid = threadIdx.x;
    int n0 = blockIdx.x * 64;

    for (int i = tid; i < 192 * 16; i += 256) Ws[i] = Wlin[i];
    // load 64 emb rows (192 floats each) coalesced: 4 row-groups of 64 threads
    {
        int col = tid & 63;
        int rbase = (tid >> 6) * 16;
#pragma unroll
        for (int r = 0; r < 16; r++) {
            int row = rbase + r;
            int n = n0 + row;
            const float* src = g_emb + (size_t)n * 192;
#pragma unroll
            for (int p = 0; p < 3; p++)
                es[row][p * 64 + col] = (n < NN) ? src[p * 64 + col] : 0.f;
        }
    }
    __syncthreads();

    int c  = tid & 15;          // class
    int ng = tid >> 4;          // node group 0..15
    int nb = ng * 4;            // local node base
    float bias = blin[c];
    float acc[4] = {bias, bias, bias, bias};

#pragma unroll 8
    for (int k = 0; k < 192; k++) {
        float w = Ws[k * 16 + c];
        acc[0] = fmaf(es[nb + 0][k], w, acc[0]);
        acc[1] = fmaf(es[nb + 1][k], w, acc[1]);
        acc[2] = fmaf(es[nb + 2][k], w, acc[2]);
        acc[3] = fmaf(es[nb + 3][k], w, acc[3]);
    }

#pragma unroll
    for (int i = 0; i < 4; i++) {
        float a = acc[i];
        float m = a;
#pragma unroll
        for (int s = 8; s >= 1; s >>= 1)
            m = fmaxf(m, __shfl_xor_sync(0xFFFFFFFFu, m, s));
        float ex = __expf(a - m);
        float sum = ex;
#pragma unroll
        for (int s = 8; s >= 1; s >>= 1)
            sum += __shfl_xor_sync(0xFFFFFFFFu, sum, s);
        int n = n0 + nb + i;
        if (n < NN) out[n * 16 + c] = a - m - logf(sum);
    }
}

// ---------------------------------------------------------------
extern "C" void kernel_launch(void* const* d_in, const int* in_sizes, int n_in,
                              void* d_out, int out_size) {
    const float* x    = (const float*)d_in[0];
    const int*   ei   = (const int*)  d_in[1];
    const float* W1   = (const float*)d_in[2];
    const float* b1   = (const float*)d_in[3];
    const float* W2   = (const float*)d_in[4];
    const float* b2   = (const float*)d_in[5];
    const float* W3   = (const float*)d_in[6];
    const float* b3   = (const float*)d_in[7];
    const float* Wlin = (const float*)d_in[8];
    const float* blin = (const float*)d_in[9];
    float* out = (float*)d_out;

    const int* rows = ei;        // targets
    const int* cols = ei + EE;   // sources

    // ---- CSR build ----
    k_hist     <<<(EE + 255) / 256, 256>>>(rows);
    k_blocksum <<<NBLK, 256>>>();
    k_scanbsum <<<1, 256>>>();
    k_finalize <<<NBLK, 256>>>();
    k_place    <<<(EE + 255) / 256, 256>>>(rows, cols);

    // ---- 3 GCN layers ----
    const float* Wb[3][2] = { {W1, b1}, {W2, b2}, {W3, b3} };
    for (int L = 0; L < 3; L++) {
        k_matmul<<<(NN + 63) / 64, 256>>>(x, L, Wb[L][0]);
        k_agg   <<<(NN * 32 + 255) / 256, 256>>>(Wb[L][1], L * 64);
    }
    k_final<<<(NN + 63) / 64, 256>>>(Wlin, blin, out);
}